// round 10
// baseline (speedup 1.0000x reference)
#include <cuda_runtime.h>
#include <cstdint>

#define NTOT (16*64*256*256)
#define CHW  (64*256*256)
#define HW   (256*256)

__device__ short g_bufA[NTOT];          // pw outputs (int16 acc)
__device__ short g_bufB[NTOT];          // dw1 output (int16 acc)
__device__ unsigned g_maxX;             // float bits of max|x|
__device__ int g_maxA1, g_maxA3;        // int max|acc| of pw1 / pw2 outputs
__device__ int g_mp[64], g_mn[64];      // per-channel max(acc), max(-acc) of dw1 out
__device__ float g_maxY3f;              // pw2 publishes max|y3| for dw2
__device__ float g_swp1, g_swf1, g_swp2, g_swf2;
__device__ unsigned g_wp1[1024];        // packed int8 weights [co][k] (k = ci/4)
__device__ unsigned g_wp2[1024];
__device__ int g_wf1[576];              // depthwise int weights [c][9]
__device__ int g_wf2[576];

__device__ __forceinline__ unsigned prmt(unsigned a, unsigned b, unsigned s) {
    unsigned d;
    asm("prmt.b32 %0,%1,%2,%3;" : "=r"(d) : "r"(a), "r"(b), "r"(s));
    return d;
}
__device__ __forceinline__ unsigned pack4s(int q0, int q1, int q2, int q3) {
    unsigned t, d;
    int z = 0;
    asm("cvt.pack.sat.s8.s32.b32 %0, %1, %2, %3;" : "=r"(t) : "r"(q3), "r"(q2), "r"(z));
    asm("cvt.pack.sat.s8.s32.b32 %0, %1, %2, %3;" : "=r"(d) : "r"(q1), "r"(q0), "r"(t));
    return d;
}
__device__ __forceinline__ unsigned packs16(int a, int b) {
    unsigned d;
    asm("cvt.pack.sat.s16.s32 %0, %1, %2;" : "=r"(d) : "r"(b), "r"(a));
    return d;
}
// warp int8 MMA: D(16x8) += A(16x32) * B(32x8), s8 x s8 -> s32
__device__ __forceinline__ void imma(int* d, const unsigned* a, unsigned b0, unsigned b1) {
    asm volatile(
        "mma.sync.aligned.m16n8k32.row.col.s32.s8.s8.s32 "
        "{%0,%1,%2,%3},{%4,%5,%6,%7},{%8,%9},{%0,%1,%2,%3};"
        : "+r"(d[0]), "+r"(d[1]), "+r"(d[2]), "+r"(d[3])
        : "r"(a[0]), "r"(a[1]), "r"(a[2]), "r"(a[3]), "r"(b0), "r"(b1));
}

// ---------------- prep: zero maxes, quantize all weights (1 block) ----------
__global__ void k_prep(const float* __restrict__ wp1, const float* __restrict__ wf1,
                       const float* __restrict__ wp2, const float* __restrict__ wf2) {
    __shared__ float red[256];
    int tid = threadIdx.x;
    if (tid == 0) { g_maxX = 0u; g_maxA1 = 0; g_maxA3 = 0; }
    if (tid < 64) { g_mp[tid] = 0; g_mn[tid] = 0; }

    float m = 0.f;
    for (int i = tid; i < 4096; i += 256) m = fmaxf(m, fabsf(wp1[i]));
    red[tid] = m; __syncthreads();
    for (int s = 128; s > 0; s >>= 1) { if (tid < s) red[tid] = fmaxf(red[tid], red[tid+s]); __syncthreads(); }
    float s1 = red[0] / 7.0f + 1e-12f;
    __syncthreads();
    for (int i = tid; i < 1024; i += 256) {
        int co = i >> 4, k = i & 15;
        unsigned pk = 0;
        for (int j = 0; j < 4; j++) {
            float w = wp1[co*64 + k*4 + j];
            int q = __float2int_rn(__fdiv_rn(w, s1));
            q = max(-7, min(7, q));
            pk |= (unsigned)(q & 255) << (8*j);
        }
        g_wp1[i] = pk;
    }
    if (tid == 0) g_swp1 = s1;

    m = 0.f;
    for (int i = tid; i < 576; i += 256) m = fmaxf(m, fabsf(wf1[i]));
    red[tid] = m; __syncthreads();
    for (int s = 128; s > 0; s >>= 1) { if (tid < s) red[tid] = fmaxf(red[tid], red[tid+s]); __syncthreads(); }
    float s2 = red[0] / 7.0f + 1e-12f;
    __syncthreads();
    for (int i = tid; i < 576; i += 256) {
        int q = __float2int_rn(__fdiv_rn(wf1[i], s2));
        g_wf1[i] = max(-7, min(7, q));
    }
    if (tid == 0) g_swf1 = s2;

    m = 0.f;
    for (int i = tid; i < 4096; i += 256) m = fmaxf(m, fabsf(wp2[i]));
    red[tid] = m; __syncthreads();
    for (int s = 128; s > 0; s >>= 1) { if (tid < s) red[tid] = fmaxf(red[tid], red[tid+s]); __syncthreads(); }
    float s3 = red[0] / 7.0f + 1e-12f;
    __syncthreads();
    for (int i = tid; i < 1024; i += 256) {
        int co = i >> 4, k = i & 15;
        unsigned pk = 0;
        for (int j = 0; j < 4; j++) {
            float w = wp2[co*64 + k*4 + j];
            int q = __float2int_rn(__fdiv_rn(w, s3));
            q = max(-7, min(7, q));
            pk |= (unsigned)(q & 255) << (8*j);
        }
        g_wp2[i] = pk;
    }
    if (tid == 0) g_swp2 = s3;

    m = 0.f;
    for (int i = tid; i < 576; i += 256) m = fmaxf(m, fabsf(wf2[i]));
    red[tid] = m; __syncthreads();
    for (int s = 128; s > 0; s >>= 1) { if (tid < s) red[tid] = fmaxf(red[tid], red[tid+s]); __syncthreads(); }
    float s4 = red[0] / 7.0f + 1e-12f;
    __syncthreads();
    for (int i = tid; i < 576; i += 256) {
        int q = __float2int_rn(__fdiv_rn(wf2[i], s4));
        g_wf2[i] = max(-7, min(7, q));
    }
    if (tid == 0) g_swf2 = s4;
}

// ---------------- global max|x| ----------------
__global__ void __launch_bounds__(256) k_maxabs(const float4* __restrict__ x) {
    int base = blockIdx.x * 256 + threadIdx.x;
    float m = 0.f;
    #pragma unroll 8
    for (int it = 0; it < 32; it++) {
        float4 v = __ldcs(x + base + it * (2048 * 256));
        m = fmaxf(m, fmaxf(fmaxf(fabsf(v.x), fabsf(v.y)), fmaxf(fabsf(v.z), fabsf(v.w))));
    }
    #pragma unroll
    for (int o = 16; o; o >>= 1) m = fmaxf(m, __shfl_xor_sync(0xffffffffu, m, o));
    if ((threadIdx.x & 31) == 0) atomicMax(&g_maxX, __float_as_uint(m));
}

// ---------------- 1x1 conv via warp mma.sync int8 ---------------------------
// CTA: 256 px x 64 co x 64 ci; warp w: px [w*32, w*32+32), all 64 co.
// Per warp: 2 m-tiles x 8 n-tiles x 2 k-steps of m16n8k32.
__global__ void __launch_bounds__(256, 2) k_pw(int which, const float* __restrict__ xf,
                                               const float* __restrict__ alpha) {
    extern __shared__ short obuf[];      // [64 co][272 px pitch] int16
    __shared__ float rpS[64], rnS[64], fred[64];
    __shared__ int sred[8];

    const int P = 272;
    int tid = threadIdx.x;
    int wid = tid >> 5, lane = tid & 31;
    int g = lane >> 2, tig = lane & 3;
    int n = blockIdx.y;
    int px0 = blockIdx.x << 8;

    // ---- scale preamble ----
    float s_x = __uint_as_float(g_maxX) / 127.0f + 1e-12f;
    float inv0 = 0.f;
    if (which == 0) {
        inv0 = 1.0f / s_x;
    } else {
        float cmul1 = s_x * g_swp1;
        float s_y1 = ((float)g_maxA1 * cmul1) / 127.0f + 1e-12f;
        float cmul2 = s_y1 * g_swf1;
        if (tid < 64) {
            float a = alpha[tid];
            rnS[tid] = a;
            float mpf = (float)g_mp[tid] * cmul2;
            float mnf = a * ((float)g_mn[tid] * cmul2);
            fred[tid] = fmaxf(mpf, fabsf(mnf));
        }
        __syncthreads();
        if (tid < 32) {
            float mm = fmaxf(fred[tid], fred[tid + 32]);
            #pragma unroll
            for (int o = 16; o; o >>= 1) mm = fmaxf(mm, __shfl_xor_sync(0xffffffffu, mm, o));
            if (tid == 0) { fred[0] = mm; g_maxY3f = mm; }
        }
        __syncthreads();
        float s3 = fred[0] / 127.0f + 1e-12f;
        float inv3 = 1.0f / s3;
        if (tid < 64) {
            float rp = cmul2 * inv3;
            rpS[tid] = rp;
            rnS[tid] = rnS[tid] * rp;
        }
        __syncthreads();
    }

    // ---- load + quantize A fragments directly into registers ----
    // aw[m][ks][i]: px = wid*32 + m*16 + g + 8*(i&1); ci0 = 4*tig + 16*(i>>1) + 32*ks
    unsigned aw[2][2][4];
    if (which == 0) {
        const float* xb = xf + (size_t)n * CHW + px0;
        #pragma unroll
        for (int m = 0; m < 2; m++)
            #pragma unroll
            for (int ks = 0; ks < 2; ks++)
                #pragma unroll
                for (int i = 0; i < 4; i++) {
                    int px = wid*32 + m*16 + g + 8*(i & 1);
                    int ci0 = 4*tig + 16*(i >> 1) + 32*ks;
                    const float* p = xb + (size_t)ci0 * HW + px;
                    int q0 = __float2int_rn(p[0]        * inv0);
                    int q1 = __float2int_rn(p[HW]       * inv0);
                    int q2 = __float2int_rn(p[2*HW]     * inv0);
                    int q3 = __float2int_rn(p[3*(size_t)HW] * inv0);
                    aw[m][ks][i] = pack4s(q0, q1, q2, q3);
                }
    } else {
        const short* tb = g_bufB + (size_t)n * CHW + px0;
        #pragma unroll
        for (int m = 0; m < 2; m++)
            #pragma unroll
            for (int ks = 0; ks < 2; ks++)
                #pragma unroll
                for (int i = 0; i < 4; i++) {
                    int px = wid*32 + m*16 + g + 8*(i & 1);
                    int ci0 = 4*tig + 16*(i >> 1) + 32*ks;
                    const short* p = tb + (size_t)ci0 * HW + px;
                    int q[4];
                    #pragma unroll
                    for (int j = 0; j < 4; j++) {
                        int t = (int)p[(size_t)j * HW];
                        float r = (t > 0) ? rpS[ci0 + j] : rnS[ci0 + j];
                        q[j] = __float2int_rn((float)t * r);
                    }
                    aw[m][ks][i] = pack4s(q[0], q[1], q[2], q[3]);
                }
    }

    // ---- MMA: acc[m][n8][4] ----
    int acc[2][8][4];
    #pragma unroll
    for (int m = 0; m < 2; m++)
        #pragma unroll
        for (int n8 = 0; n8 < 8; n8++)
            #pragma unroll
            for (int r = 0; r < 4; r++) acc[m][n8][r] = 0;

    const unsigned* wq = which ? g_wp2 : g_wp1;
    #pragma unroll
    for (int ks = 0; ks < 2; ks++) {
        unsigned bb0[8], bb1[8];
        #pragma unroll
        for (int n8 = 0; n8 < 8; n8++) {
            int co = n8*8 + g;
            bb0[n8] = __ldg(&wq[(co << 4) + (ks << 3) + tig]);
            bb1[n8] = __ldg(&wq[(co << 4) + (ks << 3) + 4 + tig]);
        }
        #pragma unroll
        for (int n8 = 0; n8 < 8; n8++) {
            imma(acc[0][n8], aw[0][ks], bb0[n8], bb1[n8]);
            imma(acc[1][n8], aw[1][ks], bb0[n8], bb1[n8]);
        }
    }

    // ---- epilogue: scatter to smem transpose buffer, track min/max ----
    int mx = -(1 << 30), mn = (1 << 30);
    #pragma unroll
    for (int m = 0; m < 2; m++)
        #pragma unroll
        for (int n8 = 0; n8 < 8; n8++) {
            int co0 = n8*8 + 2*tig;
            int pxl = wid*32 + m*16 + g;
            int* a4 = acc[m][n8];
            mx = max(mx, max(max(a4[0], a4[1]), max(a4[2], a4[3])));
            mn = min(mn, min(min(a4[0], a4[1]), min(a4[2], a4[3])));
            obuf[co0*P + pxl]           = (short)a4[0];
            obuf[(co0 + 1)*P + pxl]     = (short)a4[1];
            obuf[co0*P + pxl + 8]       = (short)a4[2];
            obuf[(co0 + 1)*P + pxl + 8] = (short)a4[3];
        }
    __syncthreads();

    // ---- coalesced copy out: thread = (co = tid>>2, chunk = tid&3) ----
    {
        int co = tid >> 2, chunk = tid & 3;
        const uint4* src = (const uint4*)(obuf + co*P + chunk*64);
        uint4* dst = (uint4*)(g_bufA + (size_t)n * CHW + (size_t)co * HW + px0 + chunk*64);
        #pragma unroll
        for (int i = 0; i < 8; i++) dst[i] = src[i];
    }

    int amax = max(mx, -mn);
    amax = __reduce_max_sync(0xffffffffu, amax);
    if (lane == 0) sred[wid] = amax;
    __syncthreads();
    if (tid == 0) {
        int m2 = sred[0];
        #pragma unroll
        for (int i = 1; i < 8; i++) m2 = max(m2, sred[i]);
        atomicMax(which ? &g_maxA3 : &g_maxA1, m2);
    }
}

// ---------------- depthwise 3x3 via packed-int8 dp4a ------------------------
__global__ void __launch_bounds__(256) k_dw(int which, const float* __restrict__ alpha,
                                            const float* __restrict__ residual,
                                            float* __restrict__ dout) {
    __shared__ int sW[66][66];
    __shared__ int sred[16];

    int tid = threadIdx.x;
    int c = blockIdx.y, n = blockIdx.z;
    int r0 = blockIdx.x << 6;
    size_t poff = ((size_t)n * 64 + c) * HW;
    const short* plane = g_bufA + poff;

    float s_x = __uint_as_float(g_maxX) / 127.0f + 1e-12f;
    float cmulIn, sIn;
    if (which == 0) {
        float cm1 = s_x * g_swp1;
        cmulIn = cm1;
        sIn = ((float)g_maxA1 * cm1) / 127.0f + 1e-12f;
    } else {
        float s3 = g_maxY3f / 127.0f + 1e-12f;
        float cm3 = s3 * g_swp2;
        cmulIn = cm3;
        sIn = ((float)g_maxA3 * cm3) / 127.0f + 1e-12f;
    }
    float rqs = cmulIn * (1.0f / sIn);
    float cmulOut = sIn * (which ? g_swf2 : g_swf1);

    if (tid < 132) sW[tid >> 1][(tid & 1) ? 65 : 0] = 0;

    for (int idx = tid; idx < 66 * 64; idx += 256) {
        int r = idx >> 6, wc = idx & 63;
        int gr = r0 + r - 1;
        int word = 0;
        if (gr >= 0 && gr < 256) {
            short4 v = *(const short4*)(plane + gr * 256 + (wc << 2));
            int q0 = __float2int_rn((float)v.x * rqs);
            int q1 = __float2int_rn((float)v.y * rqs);
            int q2 = __float2int_rn((float)v.z * rqs);
            int q3 = __float2int_rn((float)v.w * rqs);
            word = (int)pack4s(q0, q1, q2, q3);
        }
        sW[r][1 + wc] = word;
    }

    const int* wqp = (which ? g_wf2 : g_wf1) + c * 9;
    int wlo[3], whi[3];
    #pragma unroll
    for (int kr = 0; kr < 3; kr++) {
        int w0 = wqp[3*kr], w1 = wqp[3*kr + 1], w2 = wqp[3*kr + 2];
        wlo[kr] = (w0 & 0xff) | ((w1 & 0xff) << 8) | ((w2 & 0xff) << 16);
        whi[kr] = wlo[kr] << 8;
    }
    float al = which ? alpha[c] : 0.f;
    __syncthreads();

    int g = tid & 63, rq4 = tid >> 6;
    int Rb = rq4 << 4;

    int A0, B0, C0, A1, B1, C1;
    {
        int L = sW[Rb][g], M = sW[Rb][1 + g], Rw = sW[Rb][2 + g];
        A0 = (int)prmt((unsigned)L, (unsigned)M, 0x6543u); B0 = M;
        C0 = (int)prmt((unsigned)M, (unsigned)Rw, 0x4321u);
        L = sW[Rb + 1][g]; M = sW[Rb + 1][1 + g]; Rw = sW[Rb + 1][2 + g];
        A1 = (int)prmt((unsigned)L, (unsigned)M, 0x6543u); B1 = M;
        C1 = (int)prmt((unsigned)M, (unsigned)Rw, 0x4321u);
    }

    if (which == 0) {
        short* oplane = g_bufB + poff;
        int tp = -(1 << 30), tmin = (1 << 30);
        #pragma unroll
        for (int i = 0; i < 16; i++) {
            int row = Rb + i + 2;
            int L = sW[row][g], M = sW[row][1 + g], Rw = sW[row][2 + g];
            int A2 = (int)prmt((unsigned)L, (unsigned)M, 0x6543u), B2 = M;
            int C2 = (int)prmt((unsigned)M, (unsigned)Rw, 0x4321u);
            int a0 = __dp4a(A0, wlo[0], __dp4a(A1, wlo[1], __dp4a(A2, wlo[2], 0)));
            int a1 = __dp4a(A0, whi[0], __dp4a(A1, whi[1], __dp4a(A2, whi[2], 0)));
            int a2 = __dp4a(B0, whi[0], __dp4a(B1, whi[1], __dp4a(B2, whi[2], 0)));
            int a3 = __dp4a(C0, whi[0], __dp4a(C1, whi[1], __dp4a(C2, whi[2], 0)));
            tp = max(tp, max(max(a0, a1), max(a2, a3)));
            tmin = min(tmin, min(min(a0, a1), min(a2, a3)));
            uint2 st;
            st.x = packs16(a0, a1);
            st.y = packs16(a2, a3);
            *(uint2*)(oplane + (r0 + Rb + i) * 256 + (g << 2)) = st;
            A0 = A1; B0 = B1; C0 = C1;
            A1 = A2; B1 = B2; C1 = C2;
        }
        tp = __reduce_max_sync(0xffffffffu, tp);
        int tn = __reduce_max_sync(0xffffffffu, -tmin);
        if ((tid & 31) == 0) { sred[(tid >> 5)*2] = tp; sred[(tid >> 5)*2 + 1] = tn; }
        __syncthreads();
        if (tid == 0) {
            int mp = sred[0], mn = sred[1];
            #pragma unroll
            for (int i2 = 1; i2 < 8; i2++) { mp = max(mp, sred[2*i2]); mn = max(mn, sred[2*i2 + 1]); }
            atomicMax(&g_mp[c], mp);
            atomicMax(&g_mn[c], mn);
        }
    } else {
        float* oplane = dout + poff;
        const float* rplane = residual + poff;
        #pragma unroll
        for (int i = 0; i < 16; i++) {
            int row = Rb + i + 2;
            int L = sW[row][g], M = sW[row][1 + g], Rw = sW[row][2 + g];
            int A2 = (int)prmt((unsigned)L, (unsigned)M, 0x6543u), B2 = M;
            int C2 = (int)prmt((unsigned)M, (unsigned)Rw, 0x4321u);
            int a0 = __dp4a(A0, wlo[0], __dp4a(A1, wlo[1], __dp4a(A2, wlo[2], 0)));
            int a1 = __dp4a(A0, whi[0], __dp4a(A1, whi[1], __dp4a(A2, whi[2], 0)));
            int a2 = __dp4a(B0, whi[0], __dp4a(B1, whi[1], __dp4a(B2, whi[2], 0)));
            int a3 = __dp4a(C0, whi[0], __dp4a(C1, whi[1], __dp4a(C2, whi[2], 0)));
            int off = (r0 + Rb + i) * 256 + (g << 2);
            float4 rv = *(const float4*)(rplane + off);
            float f0 = (float)a0 * cmulOut; f0 = (f0 > 0.f ? f0 : al * f0) + rv.x;
            float f1 = (float)a1 * cmulOut; f1 = (f1 > 0.f ? f1 : al * f1) + rv.y;
            float f2 = (float)a2 * cmulOut; f2 = (f2 > 0.f ? f2 : al * f2) + rv.z;
            float f3 = (float)a3 * cmulOut; f3 = (f3 > 0.f ? f3 : al * f3) + rv.w;
            *(float4*)(oplane + off) = make_float4(f0, f1, f2, f3);
            A0 = A1; B0 = B1; C0 = C1;
            A1 = A2; B1 = B2; C1 = C2;
        }
    }
}

extern "C" void kernel_launch(void* const* d_in, const int* in_sizes, int n_in,
                              void* d_out, int out_size) {
    const float* x   = (const float*)d_in[0];
    const float* wp1 = (const float*)d_in[1];
    const float* wf1 = (const float*)d_in[2];
    const float* wp2 = (const float*)d_in[3];
    const float* wf2 = (const float*)d_in[4];
    const float* a1  = (const float*)d_in[5];
    const float* a2  = (const float*)d_in[6];
    float* out = (float*)d_out;

    const int PW_SMEM = 64 * 272 * 2;   // 34816 B transpose buffer

    k_prep<<<1, 256>>>(wp1, wf1, wp2, wf2);
    k_maxabs<<<2048, 256>>>((const float4*)x);
    k_pw<<<dim3(256, 16), 256, PW_SMEM>>>(0, x, nullptr);
    k_dw<<<dim3(4, 64, 16), 256>>>(0, nullptr, nullptr, nullptr);
    k_pw<<<dim3(256, 16), 256, PW_SMEM>>>(1, nullptr, a1);
    k_dw<<<dim3(4, 64, 16), 256>>>(1, a2, x, out);
}